// round 3
// baseline (speedup 1.0000x reference)
#include <cuda_runtime.h>
#include <math.h>

#define NNODES 50000
#define TT 8
#define CIN 32
#define HH 128
#define COUT 32
#define EDGES 800000
#define MROWS (NNODES*TT)   /* 400000 */

// ---------------- scratch (device globals; no allocation in kernel_launch) ----
__device__ int   g_is64;
__device__ int   g_src[EDGES];
__device__ int   g_dst[EDGES];
__device__ int   g_cnt[NNODES];
__device__ int   g_off[NNODES];
__device__ int   g_cur[NNODES];
__device__ int   g_adj[EDGES];
__device__ float g_AX [(size_t)MROWS*64];      // [m=(n*8+t), 64] = [agg/deg | x]
__device__ float g_Wcat[HH*64];                // [128, 64] = [Wl | Wr]
__device__ float g_SP [(size_t)MROWS*HH];      // [m, 128]
__device__ float g_GX [(size_t)MROWS*3*HH];    // [m, 384]
__device__ float g_GH [(size_t)NNODES*3*HH];   // [n, 384]
__device__ float g_H  [(size_t)NNODES*HH];     // [n, 128]
__device__ float g_HS [(size_t)MROWS*HH];      // [m, 128]
__device__ float g_C1 [(size_t)MROWS*64];      // [m, 64]

// ---------------- edge dtype detection + conversion ---------------------------
// If edge_index is int64, every entry (node id < 50000) has zero high 32 bits.
// If it is int32, interpreting pairs as int64 puts a random node id in the high
// word; with 1024 samples the discrimination is deterministic for this data.
__global__ void detect_kernel(const void* ei) {
    const unsigned long long* p = (const unsigned long long*)ei;
    int is64 = 1;
    for (int i = 0; i < 1024; i++)
        if ((p[i] >> 32) != 0ull) { is64 = 0; break; }
    g_is64 = is64;
}

__global__ void convert_kernel(const void* ei) {
    int e = blockIdx.x * blockDim.x + threadIdx.x;
    if (e >= EDGES) return;
    int s, d;
    if (g_is64) {
        const long long* p = (const long long*)ei;
        s = (int)p[e]; d = (int)p[EDGES + e];
    } else {
        const int* p = (const int*)ei;
        s = p[e]; d = p[EDGES + e];
    }
    // defensive clamp: never allow an out-of-range index to become a trap
    s = min(max(s, 0), NNODES - 1);
    d = min(max(d, 0), NNODES - 1);
    g_src[e] = s;
    g_dst[e] = d;
}

// ---------------- graph prep --------------------------------------------------
__global__ void zero_kernel() {
    int idx = blockIdx.x * blockDim.x + threadIdx.x;
    int stride = gridDim.x * blockDim.x;
    for (size_t i = idx; i < (size_t)NNODES*HH; i += stride) g_H[i] = 0.f;
    for (int i = idx; i < NNODES; i += stride) g_cnt[i] = 0;
}

__global__ void count_kernel() {
    int e = blockIdx.x * blockDim.x + threadIdx.x;
    if (e < EDGES) atomicAdd(&g_cnt[g_dst[e]], 1);
}

// single block: exclusive scan of g_cnt -> g_off, g_cur
__global__ void scan_kernel() {
    __shared__ int partial[1024];
    const int CH = (NNODES + 1023) / 1024;
    int t = threadIdx.x;
    int begin = t * CH;
    int end   = min(begin + CH, NNODES);
    int s = 0;
    for (int i = begin; i < end; i++) s += g_cnt[i];
    partial[t] = s;
    __syncthreads();
    #pragma unroll
    for (int d = 1; d < 1024; d <<= 1) {
        int v = (t >= d) ? partial[t - d] : 0;
        __syncthreads();
        partial[t] += v;
        __syncthreads();
    }
    int off = partial[t] - s;     // exclusive prefix for this chunk
    for (int i = begin; i < end; i++) {
        g_off[i] = off;
        g_cur[i] = off;
        off += g_cnt[i];
    }
}

__global__ void fill_kernel() {
    int e = blockIdx.x * blockDim.x + threadIdx.x;
    if (e >= EDGES) return;
    int pos = atomicAdd(&g_cur[g_dst[e]], 1);
    g_adj[pos] = g_src[e];
}

// one 256-thread block per node: thread idx=(t*32+c) accumulates channel idx
// over the neighbor list, then writes AX[m,64] = [agg/deg | x].
__global__ void __launch_bounds__(256) gather_kernel(const float* __restrict__ x) {
    int n   = blockIdx.x;
    int idx = threadIdx.x;
    int beg = g_off[n];
    int cnt = g_cnt[n];
    float s = 0.f;
    for (int p = beg; p < beg + cnt; p++) {
        int src = g_adj[p];                       // broadcast load
        s += x[(size_t)src * 256 + idx];
    }
    float dg = fmaxf((float)cnt, 1.f);
    int t = idx >> 5, c = idx & 31;
    size_t m = (size_t)n * 8 + t;
    g_AX[m * 64 + c]      = s / dg;
    g_AX[m * 64 + 32 + c] = x[(size_t)n * 256 + idx];
}

__global__ void wcat_kernel(const float* __restrict__ Wl, const float* __restrict__ Wr) {
    int idx = blockIdx.x * blockDim.x + threadIdx.x;
    if (idx >= HH*64) return;
    int j = idx >> 6, c = idx & 63;
    g_Wcat[idx] = (c < 32) ? Wl[j*32 + c] : Wr[j*32 + (c-32)];
}

// ---------------- GRU pointwise ----------------------------------------------
__global__ void gru_kernel(int t) {
    int idx = blockIdx.x * blockDim.x + threadIdx.x;
    if (idx >= NNODES*HH) return;
    int i = idx >> 7, j = idx & 127;
    size_t m = (size_t)i*8 + t;
    float gxr = g_GX[m*384 + j];
    float gxz = g_GX[m*384 + 128 + j];
    float gxn = g_GX[m*384 + 256 + j];
    float ghr = g_GH[(size_t)i*384 + j];
    float ghz = g_GH[(size_t)i*384 + 128 + j];
    float ghn = g_GH[(size_t)i*384 + 256 + j];
    float r  = 1.f / (1.f + expf(-(gxr + ghr)));
    float z  = 1.f / (1.f + expf(-(gxz + ghz)));
    float nn = tanhf(gxn + r*ghn);
    float h  = g_H[idx];
    float hn = (1.f - z)*nn + z*h;
    g_H[idx] = hn;
    g_HS[m*128 + j] = hn;
}

// warp per row: cls[m] = sigmoid(dot(C1[m,:64], w2) + b2)
__global__ void cls_kernel(const float* __restrict__ w2, const float* __restrict__ b2,
                           float* __restrict__ out) {
    int g = blockIdx.x * blockDim.x + threadIdx.x;
    int warp = g >> 5;
    int lane = threadIdx.x & 31;
    if (warp >= MROWS) return;
    float s = g_C1[(size_t)warp*64 + lane]      * w2[lane]
            + g_C1[(size_t)warp*64 + 32 + lane] * w2[32 + lane];
    #pragma unroll
    for (int o = 16; o; o >>= 1) s += __shfl_xor_sync(0xffffffffu, s, o);
    if (lane == 0) out[warp] = 1.f / (1.f + expf(-(s + b2[0])));
}

// ---------------- tiled SGEMM: C[m,n] = act( sum_k A[m,k]*W[n,k] + bias[n] ) --
template<int BM, int BN, int BK, int TM, int TN, int ACT>
__global__ void __launch_bounds__((BM/TM)*(BN/TN))
gemm_atb(int M, int N, int K,
         const float* __restrict__ A, int rsA,
         const float* __restrict__ W,        // [N, K] row-major
         const float* __restrict__ bias,
         float* __restrict__ C, int rsC)
{
    constexpr int THREADS = (BM/TM)*(BN/TN);
    constexpr int A4 = BM*BK/4;
    constexpr int B4 = BN*BK/4;
    constexpr int APT = (A4 + THREADS - 1) / THREADS;
    constexpr int BPT = (B4 + THREADS - 1) / THREADS;

    __shared__ float As[BK][BM+4];
    __shared__ float Bs[BK][BN+4];

    const int tid  = threadIdx.x;
    const int bm   = blockIdx.x * BM;
    const int bn   = blockIdx.y * BN;
    const int tCol = tid % (BN/TN);
    const int tRow = tid / (BN/TN);

    float acc[TM][TN] = {};
    float4 aReg[APT];
    float4 bReg[BPT];

    auto loadRegs = [&](int kt) {
        #pragma unroll
        for (int u = 0; u < APT; u++) {
            int i = tid + u*THREADS;
            if (i < A4) {
                int m  = i / (BK/4);
                int k4 = i % (BK/4);
                int row = bm + m;
                aReg[u] = (row < M)
                    ? *(const float4*)(A + (size_t)row*rsA + kt + k4*4)
                    : make_float4(0.f, 0.f, 0.f, 0.f);
            }
        }
        #pragma unroll
        for (int u = 0; u < BPT; u++) {
            int i = tid + u*THREADS;
            if (i < B4) {
                int n  = i / (BK/4);
                int k4 = i % (BK/4);
                bReg[u] = *(const float4*)(W + (size_t)(bn + n)*K + kt + k4*4);
            }
        }
    };
    auto storeSmem = [&]() {
        #pragma unroll
        for (int u = 0; u < APT; u++) {
            int i = tid + u*THREADS;
            if (i < A4) {
                int m = i / (BK/4);
                int k = (i % (BK/4)) * 4;
                As[k+0][m] = aReg[u].x; As[k+1][m] = aReg[u].y;
                As[k+2][m] = aReg[u].z; As[k+3][m] = aReg[u].w;
            }
        }
        #pragma unroll
        for (int u = 0; u < BPT; u++) {
            int i = tid + u*THREADS;
            if (i < B4) {
                int n = i / (BK/4);
                int k = (i % (BK/4)) * 4;
                Bs[k+0][n] = bReg[u].x; Bs[k+1][n] = bReg[u].y;
                Bs[k+2][n] = bReg[u].z; Bs[k+3][n] = bReg[u].w;
            }
        }
    };

    loadRegs(0);
    storeSmem();
    __syncthreads();

    for (int kt = BK; kt <= K; kt += BK) {
        if (kt < K) loadRegs(kt);   // overlap next global loads with compute
        #pragma unroll
        for (int kk = 0; kk < BK; kk++) {
            float a[TM], b[TN];
            #pragma unroll
            for (int i = 0; i < TM; i++) a[i] = As[kk][tRow*TM + i];
            #pragma unroll
            for (int j = 0; j < TN; j++) b[j] = Bs[kk][tCol*TN + j];
            #pragma unroll
            for (int i = 0; i < TM; i++)
                #pragma unroll
                for (int j = 0; j < TN; j++)
                    acc[i][j] = fmaf(a[i], b[j], acc[i][j]);
        }
        __syncthreads();
        if (kt < K) { storeSmem(); __syncthreads(); }
    }

    #pragma unroll
    for (int i = 0; i < TM; i++) {
        int row = bm + tRow*TM + i;
        if (row >= M) continue;
        #pragma unroll
        for (int j = 0; j < TN; j++) {
            int n = bn + tCol*TN + j;
            float v = acc[i][j] + bias[n];
            if (ACT == 1) v = fmaxf(v, 0.f);
            C[(size_t)row*rsC + n] = v;
        }
    }
}

// ---------------- launch ------------------------------------------------------
extern "C" void kernel_launch(void* const* d_in, const int* in_sizes, int n_in,
                              void* d_out, int out_size)
{
    const float* x     = (const float*)d_in[0];
    const void*  ei    = d_in[1];                 // int32 OR int64 — detected on device
    const float* Wl    = (const float*)d_in[2];
    const float* bl    = (const float*)d_in[3];
    const float* Wr    = (const float*)d_in[4];
    const float* W_ih  = (const float*)d_in[5];
    const float* b_ih  = (const float*)d_in[6];
    const float* W_hh  = (const float*)d_in[7];
    const float* b_hh  = (const float*)d_in[8];
    const float* W_rec = (const float*)d_in[9];
    const float* b_rec = (const float*)d_in[10];
    const float* W_c1  = (const float*)d_in[11];
    const float* b_c1  = (const float*)d_in[12];
    const float* W_c2  = (const float*)d_in[13];
    const float* b_c2  = (const float*)d_in[14];

    float* out      = (float*)d_out;
    float* outRecon = out;                                // [N,T,32] flat, row m
    float* outCls   = out + (size_t)MROWS * COUT;         // [N,T] flat, row m

    float *pAX, *pWcat, *pSP, *pGX, *pGH, *pH, *pHS, *pC1;
    cudaGetSymbolAddress((void**)&pAX,   g_AX);
    cudaGetSymbolAddress((void**)&pWcat, g_Wcat);
    cudaGetSymbolAddress((void**)&pSP,   g_SP);
    cudaGetSymbolAddress((void**)&pGX,   g_GX);
    cudaGetSymbolAddress((void**)&pGH,   g_GH);
    cudaGetSymbolAddress((void**)&pH,    g_H);
    cudaGetSymbolAddress((void**)&pHS,   g_HS);
    cudaGetSymbolAddress((void**)&pC1,   g_C1);

    // graph prep: detect dtype -> convert(+clamp) -> count -> scan -> fill -> gather
    detect_kernel<<<1, 1>>>(ei);
    convert_kernel<<<(EDGES + 255)/256, 256>>>(ei);
    zero_kernel<<<1024, 256>>>();
    wcat_kernel<<<(HH*64 + 255)/256, 256>>>(Wl, Wr);
    count_kernel<<<(EDGES + 255)/256, 256>>>();
    scan_kernel<<<1, 1024>>>();
    fill_kernel<<<(EDGES + 255)/256, 256>>>();
    gather_kernel<<<NNODES, 256>>>(x);

    // SP = relu(AX @ Wcat^T + bl): [400000,64] -> [400000,128]
    gemm_atb<128,128,16,8,8,1><<<dim3((MROWS+127)/128, 1), 256>>>(
        MROWS, 128, 64, pAX, 64, pWcat, bl, pSP, 128);

    // GX = SP @ W_ih^T + b_ih: [400000,128] -> [400000,384]
    gemm_atb<128,128,16,8,8,0><<<dim3((MROWS+127)/128, 3), 256>>>(
        MROWS, 384, 128, pSP, 128, W_ih, b_ih, pGX, 384);

    // recurrence
    for (int t = 0; t < TT; t++) {
        // GH = H @ W_hh^T + b_hh: [50000,128] -> [50000,384]
        gemm_atb<128,128,16,8,8,0><<<dim3((NNODES+127)/128, 3), 256>>>(
            NNODES, 384, 128, pH, 128, W_hh, b_hh, pGH, 384);
        gru_kernel<<<(NNODES*HH + 255)/256, 256>>>(t);
    }

    // recon = HS @ W_rec^T + b_rec -> out (row m, ld 32)
    gemm_atb<128,32,16,8,2,0><<<dim3((MROWS+127)/128, 1), 256>>>(
        MROWS, 32, 128, pHS, 128, W_rec, b_rec, outRecon, 32);

    // C1 = relu(HS @ W_c1^T + b_c1)
    gemm_atb<128,64,16,8,4,1><<<dim3((MROWS+127)/128, 1), 256>>>(
        MROWS, 64, 128, pHS, 128, W_c1, b_c1, pC1, 64);

    // cls = sigmoid(C1 @ w_c2 + b_c2)
    cls_kernel<<<(MROWS*32 + 255)/256, 256>>>(W_c2, b_c2, outCls);
}